// round 7
// baseline (speedup 1.0000x reference)
#include <cuda_runtime.h>
#include <cuda_fp16.h>
#include <math.h>
#include <stdint.h>

#define N_NODES   100000
#define N_EDGES   200000
#define EMB       300
#define EMB2      600
#define NUM_LAYER 5
#define NUM_GRAPHS 5000
#define BN_EPS    1e-5f

// ---------------- device scratch (allocation-free) ----------------
__device__ __align__(16) float g_h[N_NODES * EMB];
__device__ __align__(16) float g_agg[N_NODES * EMB];
__device__ __align__(16) float g_t[N_NODES * EMB2];
__device__ __align__(16) float g_tab[9 * EMB];
__device__ float g_stats[2 * EMB];
__device__ float g_counts[NUM_GRAPHS];
// transposed + split weights (fp16 hi/lo), zero-padded: max 384x640 = 245760
__device__ __align__(16) __half g_wth[245760];
__device__ __align__(16) __half g_wtl[245760];

__device__ __forceinline__ uint32_t smem_u32(const void* p) {
    uint32_t a;
    asm("{ .reg .u64 t; cvta.to.shared.u64 t, %1; cvt.u32.u64 %0, t; }" : "=r"(a) : "l"(p));
    return a;
}

// ---------------- h0 = x_emb1[x0] + x_emb2[x1] ----------------
__global__ void init_h_kernel(const int* __restrict__ x,
                              const float* __restrict__ e1,
                              const float* __restrict__ e2) {
    int idx = blockIdx.x * blockDim.x + threadIdx.x;
    if (idx >= N_NODES * EMB) return;
    int i = idx / EMB, c = idx - i * EMB;
    int a = x[2 * i], b = x[2 * i + 1];
    g_h[idx] = e1[a * EMB + c] + e2[b * EMB + c];
}

// ---------------- per-layer eemb table ----------------
__global__ void build_tab_kernel(const float* __restrict__ e1,
                                 const float* __restrict__ e2, int l) {
    int idx = blockIdx.x * blockDim.x + threadIdx.x;
    if (idx >= 9 * EMB) return;
    int t = idx / EMB, c = idx - t * EMB;
    int a = t / 3, b = t - a * 3;
    g_tab[idx] = e1[(l * 6 + a) * EMB + c] + e2[(l * 3 + b) * EMB + c];
}

__global__ void zero_stats_kernel() {
    int idx = blockIdx.x * blockDim.x + threadIdx.x;
    if (idx < 2 * EMB) g_stats[idx] = 0.f;
}

// ---------------- agg = h + tab[0]  (first layer only) ----------------
__global__ void init_agg_kernel() {
    int idx = blockIdx.x * blockDim.x + threadIdx.x;
    if (idx >= N_NODES * EMB) return;
    g_agg[idx] = g_h[idx] + g_tab[idx % EMB];
}

// ---------------- edge scatter: agg[dst] += h[src] + tab[attr] ----------------
__global__ __launch_bounds__(256) void scatter_edges_kernel(
        const int* __restrict__ ei, const int* __restrict__ ea) {
    int e = blockIdx.x * 8 + (threadIdx.x >> 5);
    if (e >= N_EDGES) return;
    int lane = threadIdx.x & 31;
    int src = ei[e];
    int dst = ei[N_EDGES + e];
    int t = ea[2 * e] * 3 + ea[2 * e + 1];
    const float4* hs = (const float4*)(g_h + (size_t)src * EMB);
    const float4* tb = (const float4*)(g_tab + t * EMB);
    float* ag = g_agg + (size_t)dst * EMB;
    #pragma unroll
    for (int i = lane; i < EMB / 4; i += 32) {
        float4 hv = hs[i];
        float4 tv = tb[i];
        atomicAdd(&ag[4 * i + 0], hv.x + tv.x);
        atomicAdd(&ag[4 * i + 1], hv.y + tv.y);
        atomicAdd(&ag[4 * i + 2], hv.z + tv.z);
        atomicAdd(&ag[4 * i + 3], hv.w + tv.w);
    }
}

// ---------------- weight transpose + fp16 hi/lo split ----------------
__global__ void transpose_split_kernel(const float* __restrict__ W,
                                       int N, int K, int Npad, int Kpad) {
    __shared__ float tile[32][33];
    int tx = threadIdx.x, ty = threadIdx.y;
    int nb = blockIdx.x * 32, kb = blockIdx.y * 32;
    #pragma unroll
    for (int j = 0; j < 4; ++j) {
        int gk = kb + ty + j * 8, gn = nb + tx;
        tile[ty + j * 8][tx] = (gk < K && gn < N) ? W[(size_t)gk * N + gn] : 0.f;
    }
    __syncthreads();
    #pragma unroll
    for (int j = 0; j < 4; ++j) {
        int gn = nb + ty + j * 8, gk = kb + tx;
        if (gn < Npad && gk < Kpad) {
            float v = tile[tx][ty + j * 8];
            __half hi = __float2half_rn(v);
            __half lo = __float2half_rn(v - __half2float(hi));
            g_wth[(size_t)gn * Kpad + gk] = hi;
            g_wtl[(size_t)gn * Kpad + gk] = lo;
        }
    }
}

// ====== 3-term split-fp16 tensor GEMM, 2-stage cp.async pipeline ======
// Block 128x128, K-tile 32, 8 warps x (64x32), mma.m16n8k16.f16, ldmatrix.
#define KT 32
#define WSTRIDE 20                         // words per smem row = 80 B
#define MATW (128 * WSTRIDE)               // 2560 words per matrix
#define STAGEW (4 * MATW)                  // Ah, Al, Bh, Bl
#define GEMM_SMEM (2 * STAGEW * 4)         // 81920 bytes

__device__ __forceinline__ void mma16f(float* c, const uint32_t* a, const uint32_t* b) {
    asm volatile(
        "mma.sync.aligned.m16n8k16.row.col.f32.f16.f16.f32 "
        "{%0,%1,%2,%3},{%4,%5,%6,%7},{%8,%9},{%0,%1,%2,%3};\n"
        : "+f"(c[0]), "+f"(c[1]), "+f"(c[2]), "+f"(c[3])
        : "r"(a[0]), "r"(a[1]), "r"(a[2]), "r"(a[3]), "r"(b[0]), "r"(b[1]));
}
__device__ __forceinline__ void ldmx4(uint32_t* r, uint32_t addr) {
    asm volatile("ldmatrix.sync.aligned.m8n8.x4.shared.b16 {%0,%1,%2,%3}, [%4];"
        : "=r"(r[0]), "=r"(r[1]), "=r"(r[2]), "=r"(r[3]) : "r"(addr));
}
#define CP16(dst, src)  asm volatile("cp.async.cg.shared.global [%0], [%1], 16;" :: "r"(dst), "l"(src))
#define CP_COMMIT()     asm volatile("cp.async.commit_group;")
#define CP_WAIT_ALL()   asm volatile("cp.async.wait_group 0;")

__device__ __forceinline__ void split4h(float4 f, uint2& hi, uint2& lo) {
    __half h0 = __float2half_rn(f.x), h1 = __float2half_rn(f.y),
           h2 = __float2half_rn(f.z), h3 = __float2half_rn(f.w);
    __half l0 = __float2half_rn(f.x - __half2float(h0)),
           l1 = __float2half_rn(f.y - __half2float(h1)),
           l2 = __float2half_rn(f.z - __half2float(h2)),
           l3 = __float2half_rn(f.w - __half2float(h3));
    __half2 ha = __halves2half2(h0, h1), hb = __halves2half2(h2, h3);
    __half2 la = __halves2half2(l0, l1), lb = __halves2half2(l2, l3);
    hi = make_uint2(*(uint32_t*)&ha, *(uint32_t*)&hb);
    lo = make_uint2(*(uint32_t*)&la, *(uint32_t*)&lb);
}

__global__ __launch_bounds__(256) void gemm_fp16x3_kernel(
        const float* __restrict__ A,
        const __half* __restrict__ Wh,
        const __half* __restrict__ Wl,
        const float* __restrict__ bias, float* __restrict__ C,
        int M, int N, int K, int Kpad, int doRelu) {
    extern __shared__ __align__(16) uint32_t sm[];

    const int tid  = threadIdx.x;
    const int lane = tid & 31;
    const int warp = tid >> 5;
    const int g = lane >> 2;
    const int t = lane & 3;
    const int wm = (warp & 1) * 64;
    const int wn = (warp >> 1) * 32;
    const int row0 = blockIdx.y * 128;
    const int col0 = blockIdx.x * 128;

    // per-thread tile-load coords
    const int a_r  = tid >> 3, a_kq = tid & 7;          // + it*32 rows
    const int b_term = tid >> 9;                        // always 0 for 256 thr; use idx
    (void)b_term;

    // ldmatrix lane selectors
    const int l8  = lane & 7;
    const int sel = lane >> 3;
    const int lm_a_row  = l8 + ((sel & 1) << 3);
    const int lm_a_koff = ((sel >> 1) << 3) * 2;
    const int lm_b_row  = l8 + ((sel >> 1) << 3);
    const int lm_b_koff = ((sel & 1) << 3) * 2;

    float c[4][4][4] = {};
    float4 ra[4];

    const int nk = (K + KT - 1) / KT;

    // ---- preamble: A regs + B cp.async for tile 0 ----
    #pragma unroll
    for (int it = 0; it < 4; ++it) {
        int idx = tid + it * 256;
        int r = idx >> 3, kq = idx & 7;
        int gr = row0 + r, gk = kq * 4;
        ra[it] = (gr < M && gk < K) ? *(const float4*)(A + (size_t)gr * K + gk)
                                    : make_float4(0.f, 0.f, 0.f, 0.f);
    }
    {
        uint32_t s0 = smem_u32(sm);
        #pragma unroll
        for (int it = 0; it < 4; ++it) {
            int idx = tid + it * 256;
            int term = idx >> 9, rem = idx & 511;
            int r = rem >> 2, q = rem & 3;
            const __half* src = (term ? Wl : Wh) + (size_t)(col0 + r) * Kpad + q * 8;
            uint32_t dst = s0 + ((2 + term) * MATW + r * WSTRIDE + q * 4) * 4;
            CP16(dst, src);
        }
        CP_COMMIT();
    }

    for (int kt = 0; kt < nk; ++kt) {
        const int buf = kt & 1;
        uint32_t* S = sm + buf * STAGEW;
        const uint32_t sb = smem_u32(S);

        // ---- store A-split(kt) from regs ----
        #pragma unroll
        for (int it = 0; it < 4; ++it) {
            int idx = tid + it * 256;
            int r = idx >> 3, kq = idx & 7;
            uint2 hi, lo;
            split4h(ra[it], hi, lo);
            *(uint2*)&S[r * WSTRIDE + kq * 2]        = hi;
            *(uint2*)&S[MATW + r * WSTRIDE + kq * 2] = lo;
        }
        CP_WAIT_ALL();          // B(kt) landed
        __syncthreads();        // single sync per tile

        // ---- issue loads for tile kt+1 (overlap with compute) ----
        if (kt + 1 < nk) {
            int k0 = (kt + 1) * KT;
            #pragma unroll
            for (int it = 0; it < 4; ++it) {
                int idx = tid + it * 256;
                int r = idx >> 3, kq = idx & 7;
                int gr = row0 + r, gk = k0 + kq * 4;
                ra[it] = (gr < M && gk < K) ? *(const float4*)(A + (size_t)gr * K + gk)
                                            : make_float4(0.f, 0.f, 0.f, 0.f);
            }
            uint32_t sn = smem_u32(sm + (1 - buf) * STAGEW);
            #pragma unroll
            for (int it = 0; it < 4; ++it) {
                int idx = tid + it * 256;
                int term = idx >> 9, rem = idx & 511;
                int r = rem >> 2, q = rem & 3;
                const __half* src = (term ? Wl : Wh) +
                    (size_t)(col0 + r) * Kpad + k0 + q * 8;
                uint32_t dst = sn + ((2 + term) * MATW + r * WSTRIDE + q * 4) * 4;
                CP16(dst, src);
            }
            CP_COMMIT();
        }

        // ---- compute tile kt ----
        const uint32_t sAh = sb;
        const uint32_t sAl = sb + MATW * 4;
        const uint32_t sBh = sb + 2 * MATW * 4;
        const uint32_t sBl = sb + 3 * MATW * 4;
        #pragma unroll
        for (int ks = 0; ks < 2; ++ks) {
            const int ka = ks * 32 + lm_a_koff;
            const int kb = ks * 32 + lm_b_koff;
            uint32_t afh[4][4], afl[4][4], bfh[4][2], bfl[4][2];
            #pragma unroll
            for (int i = 0; i < 4; ++i) {
                uint32_t ro = (uint32_t)(wm + i * 16 + lm_a_row) * 80 + ka;
                ldmx4(afh[i], sAh + ro);
                ldmx4(afl[i], sAl + ro);
            }
            #pragma unroll
            for (int j2 = 0; j2 < 2; ++j2) {
                uint32_t ro = (uint32_t)(wn + j2 * 16 + lm_b_row) * 80 + kb;
                uint32_t r[4];
                ldmx4(r, sBh + ro);
                bfh[2 * j2][0] = r[0]; bfh[2 * j2][1] = r[1];
                bfh[2 * j2 + 1][0] = r[2]; bfh[2 * j2 + 1][1] = r[3];
                ldmx4(r, sBl + ro);
                bfl[2 * j2][0] = r[0]; bfl[2 * j2][1] = r[1];
                bfl[2 * j2 + 1][0] = r[2]; bfl[2 * j2 + 1][1] = r[3];
            }
            #pragma unroll
            for (int i = 0; i < 4; ++i)
                #pragma unroll
                for (int j = 0; j < 4; ++j) {
                    mma16f(c[i][j], afl[i], bfh[j]);
                    mma16f(c[i][j], afh[i], bfl[j]);
                    mma16f(c[i][j], afh[i], bfh[j]);
                }
        }
    }

    // ---- epilogue: bias + optional relu ----
    #pragma unroll
    for (int i = 0; i < 4; ++i) {
        int r = row0 + wm + i * 16 + g;
        #pragma unroll
        for (int j = 0; j < 4; ++j) {
            int cc = col0 + wn + j * 8 + 2 * t;
            if (cc >= N) continue;
            float bx = bias[cc], by = bias[cc + 1];
            if (r < M) {
                float2 v = make_float2(c[i][j][0] + bx, c[i][j][1] + by);
                if (doRelu) { v.x = fmaxf(v.x, 0.f); v.y = fmaxf(v.y, 0.f); }
                *(float2*)&C[(size_t)r * N + cc] = v;
            }
            int r2 = r + 8;
            if (r2 < M) {
                float2 v = make_float2(c[i][j][2] + bx, c[i][j][3] + by);
                if (doRelu) { v.x = fmaxf(v.x, 0.f); v.y = fmaxf(v.y, 0.f); }
                *(float2*)&C[(size_t)r2 * N + cc] = v;
            }
        }
    }
}

// ---------------- BN pass 1: per-channel sum ----------------
#define BNROWS 256
__global__ void bn_sum_kernel(const float* __restrict__ X) {
    int c = threadIdx.x;
    if (c >= EMB) return;
    int r0 = blockIdx.x * BNROWS;
    int r1 = min(r0 + BNROWS, N_NODES);
    float s = 0.f;
    for (int r = r0; r < r1; ++r) s += X[(size_t)r * EMB + c];
    atomicAdd(&g_stats[c], s);
}

// ---------------- BN pass 2: centered sumsq ----------------
__global__ void bn_sumsq_kernel(const float* __restrict__ X) {
    int c = threadIdx.x;
    if (c >= EMB) return;
    float mu = g_stats[c] * (1.f / N_NODES);
    int r0 = blockIdx.x * BNROWS;
    int r1 = min(r0 + BNROWS, N_NODES);
    float s = 0.f;
    for (int r = r0; r < r1; ++r) {
        float d = X[(size_t)r * EMB + c] - mu;
        s += d * d;
    }
    atomicAdd(&g_stats[EMB + c], s);
}

// ---------------- BN apply; optionally fused with next-layer agg init ----------------
__global__ void bn_apply_kernel(const float* __restrict__ X,
                                const float* __restrict__ gamma,
                                const float* __restrict__ beta,
                                int l, int doRelu, int doAgg) {
    int idx = blockIdx.x * blockDim.x + threadIdx.x;
    if (idx >= N_NODES * EMB) return;
    int c = idx % EMB;
    float mu = g_stats[c] * (1.f / N_NODES);
    float var = g_stats[EMB + c] * (1.f / N_NODES);
    float sc = rsqrtf(var + BN_EPS) * gamma[l * EMB + c];
    float v = (X[idx] - mu) * sc + beta[l * EMB + c];
    if (doRelu) v = fmaxf(v, 0.f);
    g_h[idx] = v;
    if (doAgg) g_agg[idx] = v + g_tab[c];
}

// ---------------- pooling ----------------
__global__ void pool_zero_kernel(float* __restrict__ out) {
    int idx = blockIdx.x * blockDim.x + threadIdx.x;
    if (idx < NUM_GRAPHS) g_counts[idx] = 0.f;
    if (idx < NUM_GRAPHS * EMB) out[idx] = 0.f;
}
__global__ void pool_count_kernel(const int* __restrict__ batch) {
    int i = blockIdx.x * blockDim.x + threadIdx.x;
    if (i >= N_NODES) return;
    atomicAdd(&g_counts[batch[i]], 1.f);
}
__global__ void pool_scatter_kernel(const int* __restrict__ batch,
                                    float* __restrict__ out) {
    int idx = blockIdx.x * blockDim.x + threadIdx.x;
    if (idx >= N_NODES * EMB) return;
    int i = idx / EMB, c = idx - i * EMB;
    atomicAdd(&out[(size_t)batch[i] * EMB + c], g_h[idx]);
}
__global__ void pool_div_kernel(float* __restrict__ out) {
    int idx = blockIdx.x * blockDim.x + threadIdx.x;
    if (idx >= NUM_GRAPHS * EMB) return;
    out[idx] /= fmaxf(g_counts[idx / EMB], 1.f);
}

// ---------------- launch ----------------
extern "C" void kernel_launch(void* const* d_in, const int* in_sizes, int n_in,
                              void* d_out, int out_size) {
    const int*   x        = (const int*)d_in[0];
    const int*   edge_idx = (const int*)d_in[1];
    const int*   edge_att = (const int*)d_in[2];
    const int*   batch    = (const int*)d_in[3];
    const float* x_emb1   = (const float*)d_in[4];
    const float* x_emb2   = (const float*)d_in[5];
    const float* edge_e1  = (const float*)d_in[6];
    const float* edge_e2  = (const float*)d_in[7];
    const float* W1       = (const float*)d_in[8];
    const float* b1       = (const float*)d_in[9];
    const float* W2       = (const float*)d_in[10];
    const float* b2       = (const float*)d_in[11];
    const float* gamma    = (const float*)d_in[12];
    const float* beta     = (const float*)d_in[13];
    float* out = (float*)d_out;

    const int NE = N_NODES * EMB;
    const int TPB = 256;

    cudaFuncSetAttribute(gemm_fp16x3_kernel,
                         cudaFuncAttributeMaxDynamicSharedMemorySize, GEMM_SMEM);

    init_h_kernel<<<(NE + TPB - 1) / TPB, TPB>>>(x, x_emb1, x_emb2);

    float *p_agg, *p_t;
    __half *p_wh, *p_wl;
    cudaGetSymbolAddress((void**)&p_agg, g_agg);
    cudaGetSymbolAddress((void**)&p_t, g_t);
    cudaGetSymbolAddress((void**)&p_wh, g_wth);
    cudaGetSymbolAddress((void**)&p_wl, g_wtl);

    const int MT = (N_NODES + 127) / 128;   // 782
    dim3 tb(32, 8);
    dim3 tr1(640 / 32, 320 / 32);   // GEMM1 weights: Npad=640, Kpad=320
    dim3 tr2(384 / 32, 640 / 32);   // GEMM2 weights: Npad=384, Kpad=640
    dim3 gg1(5, MT), gg2(3, MT);
    int bn_grid = (N_NODES + BNROWS - 1) / BNROWS;

    // layer-0 aggregation init
    build_tab_kernel<<<(9 * EMB + TPB - 1) / TPB, TPB>>>(edge_e1, edge_e2, 0);
    init_agg_kernel<<<(NE + TPB - 1) / TPB, TPB>>>();

    for (int l = 0; l < NUM_LAYER; ++l) {
        zero_stats_kernel<<<3, 256>>>();
        scatter_edges_kernel<<<(N_EDGES + 7) / 8, 256>>>(edge_idx, edge_att);

        // t = relu(agg @ W1[l] + b1[l])   [N, 600]
        transpose_split_kernel<<<tr1, tb>>>(W1 + (size_t)l * EMB * EMB2,
                                            EMB2, EMB, 640, 320);
        gemm_fp16x3_kernel<<<gg1, 256, GEMM_SMEM>>>(p_agg, p_wh, p_wl,
                                                    b1 + l * EMB2, p_t,
                                                    N_NODES, EMB2, EMB, 320, 1);
        // h2 = t @ W2[l] + b2[l]          [N, 300]
        transpose_split_kernel<<<tr2, tb>>>(W2 + (size_t)l * EMB2 * EMB,
                                            EMB, EMB2, 384, 640);
        gemm_fp16x3_kernel<<<gg2, 256, GEMM_SMEM>>>(p_t, p_wh, p_wl,
                                                    b2 + l * EMB, p_agg,
                                                    N_NODES, EMB, EMB2, 640, 0);

        bn_sum_kernel<<<bn_grid, 320>>>(p_agg);
        bn_sumsq_kernel<<<bn_grid, 320>>>(p_agg);

        int last = (l == NUM_LAYER - 1);
        if (!last) {
            build_tab_kernel<<<(9 * EMB + TPB - 1) / TPB, TPB>>>(edge_e1, edge_e2, l + 1);
            bn_apply_kernel<<<(NE + TPB - 1) / TPB, TPB>>>(p_agg, gamma, beta, l, 1, 1);
        } else {
            bn_apply_kernel<<<(NE + TPB - 1) / TPB, TPB>>>(p_agg, gamma, beta, l, 0, 0);
        }
    }

    pool_zero_kernel<<<(NUM_GRAPHS * EMB + TPB - 1) / TPB, TPB>>>(out);
    pool_count_kernel<<<(N_NODES + TPB - 1) / TPB, TPB>>>(batch);
    pool_scatter_kernel<<<(NE + TPB - 1) / TPB, TPB>>>(batch, out);
    pool_div_kernel<<<(NUM_GRAPHS * EMB + TPB - 1) / TPB, TPB>>>(out);
}

// round 8
// speedup vs baseline: 1.4847x; 1.4847x over previous
#include <cuda_runtime.h>
#include <cuda_fp16.h>
#include <math.h>
#include <stdint.h>

#define N_NODES   100000
#define N_EDGES   200000
#define EMB       300
#define EMB2      600
#define NUM_LAYER 5
#define NUM_GRAPHS 5000
#define BN_EPS    1e-5f

// ---------------- device scratch (allocation-free) ----------------
__device__ __align__(16) float g_h[N_NODES * EMB];
__device__ __align__(16) float g_agg[N_NODES * EMB];
__device__ __align__(16) float g_t[N_NODES * EMB2];
__device__ __align__(16) float g_tab[9 * EMB];
__device__ float g_stats[2 * EMB];     // [0:EMB) sum(y), [EMB:2EMB) sum(y^2)
__device__ float g_counts[NUM_GRAPHS];
// transposed + split weights (fp16 hi/lo), zero-padded: max 384x640 = 245760
__device__ __align__(16) __half g_wth[245760];
__device__ __align__(16) __half g_wtl[245760];

__device__ __forceinline__ uint32_t smem_u32(const void* p) {
    uint32_t a;
    asm("{ .reg .u64 t; cvta.to.shared.u64 t, %1; cvt.u32.u64 %0, t; }" : "=r"(a) : "l"(p));
    return a;
}

// ---------------- h0 = x_emb1[x0] + x_emb2[x1] ----------------
__global__ void init_h_kernel(const int* __restrict__ x,
                              const float* __restrict__ e1,
                              const float* __restrict__ e2) {
    int idx = blockIdx.x * blockDim.x + threadIdx.x;
    if (idx >= N_NODES * EMB) return;
    int i = idx / EMB, c = idx - i * EMB;
    int a = x[2 * i], b = x[2 * i + 1];
    g_h[idx] = e1[a * EMB + c] + e2[b * EMB + c];
}

// ---------------- per-layer eemb table ----------------
__global__ void build_tab_kernel(const float* __restrict__ e1,
                                 const float* __restrict__ e2, int l) {
    int idx = blockIdx.x * blockDim.x + threadIdx.x;
    if (idx >= 9 * EMB) return;
    int t = idx / EMB, c = idx - t * EMB;
    int a = t / 3, b = t - a * 3;
    g_tab[idx] = e1[(l * 6 + a) * EMB + c] + e2[(l * 3 + b) * EMB + c];
}

__global__ void zero_stats_kernel() {
    int idx = blockIdx.x * blockDim.x + threadIdx.x;
    if (idx < 2 * EMB) g_stats[idx] = 0.f;
}

// ---------------- agg = h + tab[0]  (first layer only) ----------------
__global__ void init_agg_kernel() {
    int idx = blockIdx.x * blockDim.x + threadIdx.x;
    if (idx >= N_NODES * EMB) return;
    g_agg[idx] = g_h[idx] + g_tab[idx % EMB];
}

// ---------------- edge scatter: agg[dst] += h[src] + tab[attr] ----------------
__global__ __launch_bounds__(256) void scatter_edges_kernel(
        const int* __restrict__ ei, const int* __restrict__ ea) {
    int e = blockIdx.x * 8 + (threadIdx.x >> 5);
    if (e >= N_EDGES) return;
    int lane = threadIdx.x & 31;
    int src = ei[e];
    int dst = ei[N_EDGES + e];
    int t = ea[2 * e] * 3 + ea[2 * e + 1];
    const float4* hs = (const float4*)(g_h + (size_t)src * EMB);
    const float4* tb = (const float4*)(g_tab + t * EMB);
    float* ag = g_agg + (size_t)dst * EMB;
    #pragma unroll
    for (int i = lane; i < EMB / 4; i += 32) {
        float4 hv = hs[i];
        float4 tv = tb[i];
        atomicAdd(&ag[4 * i + 0], hv.x + tv.x);
        atomicAdd(&ag[4 * i + 1], hv.y + tv.y);
        atomicAdd(&ag[4 * i + 2], hv.z + tv.z);
        atomicAdd(&ag[4 * i + 3], hv.w + tv.w);
    }
}

// ---------------- weight transpose + fp16 hi/lo split ----------------
__global__ void transpose_split_kernel(const float* __restrict__ W,
                                       int N, int K, int Npad, int Kpad) {
    __shared__ float tile[32][33];
    int tx = threadIdx.x, ty = threadIdx.y;
    int nb = blockIdx.x * 32, kb = blockIdx.y * 32;
    #pragma unroll
    for (int j = 0; j < 4; ++j) {
        int gk = kb + ty + j * 8, gn = nb + tx;
        tile[ty + j * 8][tx] = (gk < K && gn < N) ? W[(size_t)gk * N + gn] : 0.f;
    }
    __syncthreads();
    #pragma unroll
    for (int j = 0; j < 4; ++j) {
        int gn = nb + ty + j * 8, gk = kb + tx;
        if (gn < Npad && gk < Kpad) {
            float v = tile[tx][ty + j * 8];
            __half hi = __float2half_rn(v);
            __half lo = __float2half_rn(v - __half2float(hi));
            g_wth[(size_t)gn * Kpad + gk] = hi;
            g_wtl[(size_t)gn * Kpad + gk] = lo;
        }
    }
}

// ====== 3-term split-fp16 tensor GEMM (R6 structure) + fused BN stats ======
// Block 128x128, K-tile 32, 8 warps x (64x32), mma.m16n8k16.f16, ldmatrix.
#define KT 32
#define WSTRIDE 20   // words per smem row (16 data + 4 pad) = 80 B

__device__ __forceinline__ void mma16f(float* c, const uint32_t* a, const uint32_t* b) {
    asm volatile(
        "mma.sync.aligned.m16n8k16.row.col.f32.f16.f16.f32 "
        "{%0,%1,%2,%3},{%4,%5,%6,%7},{%8,%9},{%0,%1,%2,%3};\n"
        : "+f"(c[0]), "+f"(c[1]), "+f"(c[2]), "+f"(c[3])
        : "r"(a[0]), "r"(a[1]), "r"(a[2]), "r"(a[3]), "r"(b[0]), "r"(b[1]));
}
__device__ __forceinline__ void ldmx4(uint32_t* r, uint32_t addr) {
    asm volatile("ldmatrix.sync.aligned.m8n8.x4.shared.b16 {%0,%1,%2,%3}, [%4];"
        : "=r"(r[0]), "=r"(r[1]), "=r"(r[2]), "=r"(r[3]) : "r"(addr));
}

__device__ __forceinline__ void split4h(float4 f, uint2& hi, uint2& lo) {
    __half h0 = __float2half_rn(f.x), h1 = __float2half_rn(f.y),
           h2 = __float2half_rn(f.z), h3 = __float2half_rn(f.w);
    __half l0 = __float2half_rn(f.x - __half2float(h0)),
           l1 = __float2half_rn(f.y - __half2float(h1)),
           l2 = __float2half_rn(f.z - __half2float(h2)),
           l3 = __float2half_rn(f.w - __half2float(h3));
    __half2 ha = __halves2half2(h0, h1), hb = __halves2half2(h2, h3);
    __half2 la = __halves2half2(l0, l1), lb = __halves2half2(l2, l3);
    hi = make_uint2(*(uint32_t*)&ha, *(uint32_t*)&hb);
    lo = make_uint2(*(uint32_t*)&la, *(uint32_t*)&lb);
}

// doStats: skip bias (BN-invariant), accumulate per-column sum/sumsq into g_stats.
__global__ __launch_bounds__(256) void gemm_fp16x3_kernel(
        const float* __restrict__ A,
        const __half* __restrict__ Wh,
        const __half* __restrict__ Wl,
        const float* __restrict__ bias, float* __restrict__ C,
        int M, int N, int K, int Kpad, int doRelu, int doStats) {
    __shared__ __align__(16) uint32_t Ah[128 * WSTRIDE];
    __shared__ __align__(16) uint32_t Al[128 * WSTRIDE];
    __shared__ __align__(16) uint32_t Bh[128 * WSTRIDE];
    __shared__ __align__(16) uint32_t Bl[128 * WSTRIDE];

    const int tid  = threadIdx.x;
    const int lane = tid & 31;
    const int warp = tid >> 5;
    const int g = lane >> 2;
    const int t = lane & 3;
    const int wm = (warp & 1) * 64;
    const int wn = (warp >> 1) * 32;
    const int row0 = blockIdx.y * 128;
    const int col0 = blockIdx.x * 128;

    const uint32_t sAh = smem_u32(Ah), sAl = smem_u32(Al);
    const uint32_t sBh = smem_u32(Bh), sBl = smem_u32(Bl);

    // ldmatrix lane selectors
    const int l8  = lane & 7;
    const int sel = lane >> 3;
    const int a_row  = l8 + ((sel & 1) << 3);
    const int a_koff = ((sel >> 1) << 3) * 2;
    const int b_row  = l8 + ((sel >> 1) << 3);
    const int b_koff = ((sel & 1) << 3) * 2;

    float c[4][4][4] = {};
    float4 ra[4];
    uint4  rb[4];

    const int nk = (K + KT - 1) / KT;

    // ---- prefetch tile 0 ----
    #pragma unroll
    for (int it = 0; it < 4; ++it) {
        int idx = tid + it * 256;
        {
            int r = idx >> 3, kq = idx & 7;
            int gr = row0 + r, gk = kq * 4;
            ra[it] = (gr < M && gk < K) ? *(const float4*)(A + (size_t)gr * K + gk)
                                        : make_float4(0.f, 0.f, 0.f, 0.f);
        }
        {
            int term = idx >> 9, rem = idx & 511;
            int r = rem >> 2, q = rem & 3;
            rb[it] = *(const uint4*)((term ? Wl : Wh) + (size_t)(col0 + r) * Kpad + q * 8);
        }
    }

    for (int kt = 0; kt < nk; ++kt) {
        // ---- store staged tile to smem ----
        #pragma unroll
        for (int it = 0; it < 4; ++it) {
            int idx = tid + it * 256;
            {
                int r = idx >> 3, kq = idx & 7;
                uint2 hi, lo;
                split4h(ra[it], hi, lo);
                *(uint2*)&Ah[r * WSTRIDE + kq * 2] = hi;
                *(uint2*)&Al[r * WSTRIDE + kq * 2] = lo;
            }
            {
                int term = idx >> 9, rem = idx & 511;
                int r = rem >> 2, q = rem & 3;
                uint32_t* dst = term ? Bl : Bh;
                *(uint4*)&dst[r * WSTRIDE + q * 4] = rb[it];
            }
        }
        __syncthreads();

        // ---- prefetch next tile ----
        if (kt + 1 < nk) {
            int k0 = (kt + 1) * KT;
            #pragma unroll
            for (int it = 0; it < 4; ++it) {
                int idx = tid + it * 256;
                {
                    int r = idx >> 3, kq = idx & 7;
                    int gr = row0 + r, gk = k0 + kq * 4;
                    ra[it] = (gr < M && gk < K) ? *(const float4*)(A + (size_t)gr * K + gk)
                                                : make_float4(0.f, 0.f, 0.f, 0.f);
                }
                {
                    int term = idx >> 9, rem = idx & 511;
                    int r = rem >> 2, q = rem & 3;
                    rb[it] = *(const uint4*)((term ? Wl : Wh) +
                             (size_t)(col0 + r) * Kpad + k0 + q * 8);
                }
            }
        }

        // ---- compute: 2 k16-steps, ldmatrix + 48 MMAs each ----
        #pragma unroll
        for (int ks = 0; ks < 2; ++ks) {
            const int ka = ks * 32 + a_koff;
            const int kb = ks * 32 + b_koff;
            uint32_t afh[4][4], afl[4][4], bfh[4][2], bfl[4][2];
            #pragma unroll
            for (int i = 0; i < 4; ++i) {
                uint32_t ro = (uint32_t)(wm + i * 16 + a_row) * 80 + ka;
                ldmx4(afh[i], sAh + ro);
                ldmx4(afl[i], sAl + ro);
            }
            #pragma unroll
            for (int j2 = 0; j2 < 2; ++j2) {
                uint32_t ro = (uint32_t)(wn + j2 * 16 + b_row) * 80 + kb;
                uint32_t r[4];
                ldmx4(r, sBh + ro);
                bfh[2 * j2][0] = r[0]; bfh[2 * j2][1] = r[1];
                bfh[2 * j2 + 1][0] = r[2]; bfh[2 * j2 + 1][1] = r[3];
                ldmx4(r, sBl + ro);
                bfl[2 * j2][0] = r[0]; bfl[2 * j2][1] = r[1];
                bfl[2 * j2 + 1][0] = r[2]; bfl[2 * j2 + 1][1] = r[3];
            }
            #pragma unroll
            for (int i = 0; i < 4; ++i)
                #pragma unroll
                for (int j = 0; j < 4; ++j) {
                    mma16f(c[i][j], afl[i], bfh[j]);
                    mma16f(c[i][j], afh[i], bfl[j]);
                    mma16f(c[i][j], afh[i], bfh[j]);
                }
        }
        __syncthreads();
    }

    if (doStats) {
        // ---- per-column sum & sumsq (bias cancels in BN; rows>=M are exact 0) ----
        #pragma unroll
        for (int j = 0; j < 4; ++j) {
            float s0 = 0.f, q0 = 0.f, s1 = 0.f, q1 = 0.f;
            #pragma unroll
            for (int i = 0; i < 4; ++i) {
                float v0 = c[i][j][0], v1 = c[i][j][1];
                float v2 = c[i][j][2], v3 = c[i][j][3];
                s0 += v0 + v2; q0 += v0 * v0 + v2 * v2;
                s1 += v1 + v3; q1 += v1 * v1 + v3 * v3;
            }
            #pragma unroll
            for (int m = 4; m < 32; m <<= 1) {
                s0 += __shfl_xor_sync(0xFFFFFFFFu, s0, m);
                q0 += __shfl_xor_sync(0xFFFFFFFFu, q0, m);
                s1 += __shfl_xor_sync(0xFFFFFFFFu, s1, m);
                q1 += __shfl_xor_sync(0xFFFFFFFFu, q1, m);
            }
            if (lane < 4) {
                int cc = col0 + wn + j * 8 + 2 * t;
                if (cc < EMB) {
                    atomicAdd(&g_stats[cc], s0);
                    atomicAdd(&g_stats[EMB + cc], q0);
                }
                if (cc + 1 < EMB) {
                    atomicAdd(&g_stats[cc + 1], s1);
                    atomicAdd(&g_stats[EMB + cc + 1], q1);
                }
            }
        }
        // store WITHOUT bias
        #pragma unroll
        for (int i = 0; i < 4; ++i) {
            int r = row0 + wm + i * 16 + g;
            #pragma unroll
            for (int j = 0; j < 4; ++j) {
                int cc = col0 + wn + j * 8 + 2 * t;
                if (cc >= N) continue;
                if (r < M)
                    *(float2*)&C[(size_t)r * N + cc] = make_float2(c[i][j][0], c[i][j][1]);
                int r2 = r + 8;
                if (r2 < M)
                    *(float2*)&C[(size_t)r2 * N + cc] = make_float2(c[i][j][2], c[i][j][3]);
            }
        }
    } else {
        // ---- bias + optional relu ----
        #pragma unroll
        for (int i = 0; i < 4; ++i) {
            int r = row0 + wm + i * 16 + g;
            #pragma unroll
            for (int j = 0; j < 4; ++j) {
                int cc = col0 + wn + j * 8 + 2 * t;
                if (cc >= N) continue;
                float bx = bias[cc], by = bias[cc + 1];
                if (r < M) {
                    float2 v = make_float2(c[i][j][0] + bx, c[i][j][1] + by);
                    if (doRelu) { v.x = fmaxf(v.x, 0.f); v.y = fmaxf(v.y, 0.f); }
                    *(float2*)&C[(size_t)r * N + cc] = v;
                }
                int r2 = r + 8;
                if (r2 < M) {
                    float2 v = make_float2(c[i][j][2] + bx, c[i][j][3] + by);
                    if (doRelu) { v.x = fmaxf(v.x, 0.f); v.y = fmaxf(v.y, 0.f); }
                    *(float2*)&C[(size_t)r2 * N + cc] = v;
                }
            }
        }
    }
}

// ---------------- BN apply (uncentered stats); fused next-layer agg init ----------------
__global__ void bn_apply_kernel(const float* __restrict__ X,
                                const float* __restrict__ gamma,
                                const float* __restrict__ beta,
                                int l, int doRelu, int doAgg) {
    int idx = blockIdx.x * blockDim.x + threadIdx.x;
    if (idx >= N_NODES * EMB) return;
    int c = idx % EMB;
    float mu  = g_stats[c] * (1.f / N_NODES);
    float var = fmaxf(g_stats[EMB + c] * (1.f / N_NODES) - mu * mu, 0.f);
    float sc = rsqrtf(var + BN_EPS) * gamma[l * EMB + c];
    float v = (X[idx] - mu) * sc + beta[l * EMB + c];
    if (doRelu) v = fmaxf(v, 0.f);
    g_h[idx] = v;
    if (doAgg) g_agg[idx] = v + g_tab[c];
}

// ---------------- pooling ----------------
__global__ void pool_zero_kernel(float* __restrict__ out) {
    int idx = blockIdx.x * blockDim.x + threadIdx.x;
    if (idx < NUM_GRAPHS) g_counts[idx] = 0.f;
    if (idx < NUM_GRAPHS * EMB) out[idx] = 0.f;
}
__global__ void pool_count_kernel(const int* __restrict__ batch) {
    int i = blockIdx.x * blockDim.x + threadIdx.x;
    if (i >= N_NODES) return;
    atomicAdd(&g_counts[batch[i]], 1.f);
}
__global__ void pool_scatter_kernel(const int* __restrict__ batch,
                                    float* __restrict__ out) {
    int idx = blockIdx.x * blockDim.x + threadIdx.x;
    if (idx >= N_NODES * EMB) return;
    int i = idx / EMB, c = idx - i * EMB;
    atomicAdd(&out[(size_t)batch[i] * EMB + c], g_h[idx]);
}
__global__ void pool_div_kernel(float* __restrict__ out) {
    int idx = blockIdx.x * blockDim.x + threadIdx.x;
    if (idx >= NUM_GRAPHS * EMB) return;
    out[idx] /= fmaxf(g_counts[idx / EMB], 1.f);
}

// ---------------- launch ----------------
extern "C" void kernel_launch(void* const* d_in, const int* in_sizes, int n_in,
                              void* d_out, int out_size) {
    const int*   x        = (const int*)d_in[0];
    const int*   edge_idx = (const int*)d_in[1];
    const int*   edge_att = (const int*)d_in[2];
    const int*   batch    = (const int*)d_in[3];
    const float* x_emb1   = (const float*)d_in[4];
    const float* x_emb2   = (const float*)d_in[5];
    const float* edge_e1  = (const float*)d_in[6];
    const float* edge_e2  = (const float*)d_in[7];
    const float* W1       = (const float*)d_in[8];
    const float* b1       = (const float*)d_in[9];
    const float* W2       = (const float*)d_in[10];
    const float* b2       = (const float*)d_in[11];
    const float* gamma    = (const float*)d_in[12];
    const float* beta     = (const float*)d_in[13];
    float* out = (float*)d_out;

    const int NE = N_NODES * EMB;
    const int TPB = 256;

    init_h_kernel<<<(NE + TPB - 1) / TPB, TPB>>>(x, x_emb1, x_emb2);

    float *p_agg, *p_t;
    __half *p_wh, *p_wl;
    cudaGetSymbolAddress((void**)&p_agg, g_agg);
    cudaGetSymbolAddress((void**)&p_t, g_t);
    cudaGetSymbolAddress((void**)&p_wh, g_wth);
    cudaGetSymbolAddress((void**)&p_wl, g_wtl);

    const int MT = (N_NODES + 127) / 128;   // 782
    dim3 tb(32, 8);
    dim3 tr1(640 / 32, 320 / 32);   // GEMM1 weights: Npad=640, Kpad=320
    dim3 tr2(384 / 32, 640 / 32);   // GEMM2 weights: Npad=384, Kpad=640
    dim3 gg1(5, MT), gg2(3, MT);

    // layer-0 aggregation init
    build_tab_kernel<<<(9 * EMB + TPB - 1) / TPB, TPB>>>(edge_e1, edge_e2, 0);
    init_agg_kernel<<<(NE + TPB - 1) / TPB, TPB>>>();

    for (int l = 0; l < NUM_LAYER; ++l) {
        zero_stats_kernel<<<3, 256>>>();
        scatter_edges_kernel<<<(N_EDGES + 7) / 8, 256>>>(edge_idx, edge_att);

        // t = relu(agg @ W1[l] + b1[l])   [N, 600]
        transpose_split_kernel<<<tr1, tb>>>(W1 + (size_t)l * EMB * EMB2,
                                            EMB2, EMB, 640, 320);
        gemm_fp16x3_kernel<<<gg1, 256>>>(p_agg, p_wh, p_wl,
                                         b1 + l * EMB2, p_t,
                                         N_NODES, EMB2, EMB, 320, 1, 0);
        // y = t @ W2[l]   [N, 300]  (bias omitted — cancels in BN; stats fused)
        transpose_split_kernel<<<tr2, tb>>>(W2 + (size_t)l * EMB2 * EMB,
                                            EMB, EMB2, 384, 640);
        gemm_fp16x3_kernel<<<gg2, 256>>>(p_t, p_wh, p_wl,
                                         b2 + l * EMB, p_agg,
                                         N_NODES, EMB, EMB2, 640, 0, 1);

        int last = (l == NUM_LAYER - 1);
        if (!last) {
            build_tab_kernel<<<(9 * EMB + TPB - 1) / TPB, TPB>>>(edge_e1, edge_e2, l + 1);
            bn_apply_kernel<<<(NE + TPB - 1) / TPB, TPB>>>(p_agg, gamma, beta, l, 1, 1);
        } else {
            bn_apply_kernel<<<(NE + TPB - 1) / TPB, TPB>>>(p_agg, gamma, beta, l, 0, 0);
        }
    }

    pool_zero_kernel<<<(NUM_GRAPHS * EMB + TPB - 1) / TPB, TPB>>>(out);
    pool_count_kernel<<<(N_NODES + TPB - 1) / TPB, TPB>>>(batch);
    pool_scatter_kernel<<<(NE + TPB - 1) / TPB, TPB>>>(batch, out);
    pool_div_kernel<<<(NUM_GRAPHS * EMB + TPB - 1) / TPB, TPB>>>(out);
}